// round 3
// baseline (speedup 1.0000x reference)
#include <cuda_runtime.h>
#include <cuda_bf16.h>
#include <cstddef>

// CTC forward loss (alpha recursion), B=256, T=512, C=1024, L=64, S=129.
// One CTA per batch row. 160 threads:
//   - threads 0..128 : DP states (one state each)
//   - threads 0..64  : emission staging (65 unique classes: 64 labels + blank)
// Double-buffered smem alpha + emission buffers, one __syncthreads per step.
// 8-deep register prefetch ring hides DRAM gather latency.

#define NEGV (-1e30f)
#define EPSV (1e-7f)

namespace {
constexpr int Tt = 512;
constexpr int Cc = 1024;
constexpr int Ll = 64;
constexpr int Ss = 2 * Ll + 1;   // 129
constexpr int BLANK = Cc - 1;    // 1023
constexpr int NTH = 160;
constexpr int PFD = 8;           // prefetch ring depth
}

__global__ __launch_bounds__(NTH, 2)
void ctc_loss_kernel(const int* __restrict__ y_true,
                     const float* __restrict__ y_pred,
                     float* __restrict__ out)
{
    const int b   = blockIdx.x;
    const int tid = threadIdx.x;

    __shared__ float abuf[2][Ss + 4];   // alpha double buffer
    __shared__ float ebuf[2][68];       // emission double buffer (65 used)
    __shared__ int   lab[Ll];
    __shared__ int   ll_sh;

    const int* yt = y_true + b * Ll;

    if (tid < Ll) {
        int v = yt[tid];
        lab[tid] = (v < 0) ? BLANK : v;
    }
    if (tid == 0) {
        int c = 0;
        #pragma unroll 8
        for (int i = 0; i < Ll; i++) c += (yt[i] != -1) ? 1 : 0;
        ll_sh = c;
    }
    __syncthreads();

    const int ll     = ll_sh;
    const int Svalid = 2 * ll + 1;

    const float* lpb = y_pred + (size_t)b * Tt * Cc;

    // ---- DP role ----
    const int  s       = tid;
    const bool isState = (s < Ss);
    const bool valid   = isState && (s < Svalid);
    int   cls    = BLANK;
    bool  allow2 = false;
    float a0     = NEGV;
    if (isState) {
        cls    = (s & 1) ? lab[s >> 1] : BLANK;
        allow2 = (s >= 2) && (s & 1) && (cls != BLANK) && (cls != lab[(s >> 1) - 1]);
    }

    // ---- staging role ----
    const int  u       = tid;
    const bool isStage = (u < Ll + 1);
    int ucls = BLANK;
    if (isStage) ucls = (u < Ll) ? lab[u] : BLANK;

    // ---- t = 0 init : alpha0 lives in abuf[1] (iteration t=1 reads buf t&1=1)
    if (isState) {
        float av = NEGV;
        if (s < 2 && valid) av = __logf(lpb[cls] + EPSV);
        a0 = av;
        abuf[1][s] = av;
    }

    // ---- preload ring: p for times 1..PFD ; slot for time tt is (tt-1)%PFD
    float pf[PFD];
    if (isStage) {
        #pragma unroll
        for (int i = 0; i < PFD; i++) {
            int tt = 1 + i;
            if (tt > Tt - 1) tt = Tt - 1;
            pf[i] = __ldg(lpb + (size_t)tt * Cc + ucls);
        }
        ebuf[1][u] = __logf(pf[0] + EPSV);   // e[1]
    }
    __syncthreads();

    // ---- main scan: t = 1 .. T-1 ----
    for (int t0 = 1; t0 < Tt; t0 += 8) {
        #pragma unroll
        for (int j = 0; j < 8; j++) {
            const int t = t0 + j;
            if (t < Tt) {
                const int cur = t & 1;
                const int nxt = cur ^ 1;

                float anew = NEGV;
                if (isState) {
                    const float am1 = (s >= 1) ? abuf[cur][s - 1] : NEGV;
                    const float am2 = allow2   ? abuf[cur][s - 2] : NEGV;
                    const float e   = (s & 1)  ? ebuf[cur][s >> 1] : ebuf[cur][Ll];
                    const float m   = fmaxf(a0, fmaxf(am1, am2));
                    const float sum = __expf(a0 - m) + __expf(am1 - m) + __expf(am2 - m);
                    anew = valid ? (e + m + __logf(sum)) : NEGV;
                }
                if (isStage) {
                    // consume p[t+1] from slot t%PFD, produce e[t+1]
                    const float pnext = pf[t % PFD];
                    if (t + 1 < Tt) ebuf[nxt][u] = __logf(pnext + EPSV);
                    // push load for time t+PFD into slot (t-1)%PFD (its value, time t, is dead)
                    int tload = t + PFD;
                    if (tload > Tt - 1) tload = Tt - 1;
                    pf[(t - 1) % PFD] = __ldg(lpb + (size_t)tload * Cc + ucls);
                }
                if (isState) { abuf[nxt][s] = anew; a0 = anew; }
                __syncthreads();
            }
        }
    }

    // ---- epilogue: alpha_T is in abuf[(T)&1] = abuf[0]
    if (tid == 0) {
        const float al = abuf[0][2 * ll];
        const float ap = (ll > 0) ? abuf[0][2 * ll - 1] : NEGV;
        const float m  = fmaxf(al, ap);
        out[b] = -(m + __logf(__expf(al - m) + __expf(ap - m)));
    }
}

extern "C" void kernel_launch(void* const* d_in, const int* in_sizes, int n_in,
                              void* d_out, int out_size)
{
    // metadata order: y_true (int32, B*L) then y_pred (float32, B*T*C).
    // Be robust to ordering by size.
    const void* p0 = d_in[0];
    const void* p1 = d_in[1];
    const int*   y_true;
    const float* y_pred;
    if (in_sizes[0] < in_sizes[1]) {
        y_true = (const int*)p0;
        y_pred = (const float*)p1;
    } else {
        y_true = (const int*)p1;
        y_pred = (const float*)p0;
    }
    float* out = (float*)d_out;

    const int B = out_size;  // one loss per batch row
    ctc_loss_kernel<<<B, NTH>>>(y_true, y_pred, out);
}

// round 6
// speedup vs baseline: 3.9232x; 3.9232x over previous
#include <cuda_runtime.h>
#include <cuda_bf16.h>
#include <cstddef>

// CTC forward loss, probability-domain DP, warp-per-row, barrier-free.
// B=256, T=512, C=1024, L=64, S=129.
// Lane l holds states 6l..6l+5 in registers. One shfl_up per step carries
// the cross-lane neighbor. Power-of-2 renorm every 4 steps to a target max
// of 2^80 (large positive bias keeps small DP states far above the FP32
// denormal/FTZ floor); exponent accumulated in int; one log at the end.
// 8-deep register prefetch ring hides the DRAM gather.

#define FULLMASK 0xffffffffu
#define EPSV 1e-7f

namespace {
constexpr int Tt = 512;
constexpr int Cc = 1024;
constexpr int Ll = 64;
constexpr int BLANK = Cc - 1;
constexpr int Dp = 8;            // prefetch ring depth (steps)
}

__device__ __forceinline__ float pick6(float a0, float a1, float a2,
                                       float a3, float a4, float a5, int j) {
    float r = a0;
    r = (j == 1) ? a1 : r;
    r = (j == 2) ? a2 : r;
    r = (j == 3) ? a3 : r;
    r = (j == 4) ? a4 : r;
    r = (j == 5) ? a5 : r;
    return r;
}

__global__ __launch_bounds__(128, 1)
void ctc_warp_kernel(const int* __restrict__ y_true,
                     const float* __restrict__ y_pred,
                     float* __restrict__ out, int B)
{
    const int lane = threadIdx.x & 31;
    const int warp = threadIdx.x >> 5;
    const int b = blockIdx.x * 4 + warp;
    if (b >= B) return;                     // uniform per warp

    const int*   yt  = y_true + b * Ll;
    const float* lpb = y_pred + (size_t)b * Tt * Cc;

    // ---- label length via ballots (Ll = 64 = 2 x 32) ----
    const int va = yt[lane];
    const int vb = yt[lane + 32];
    const int ll = __popc(__ballot_sync(FULLMASK, va != -1)) +
                   __popc(__ballot_sync(FULLMASK, vb != -1));
    const int Svalid = 2 * ll + 1;

    // ---- labels this lane needs: indices 3*lane-1 .. 3*lane+2 ----
    auto labAt = [&](int idx) -> int {
        if (idx < 0 || idx >= Ll) return BLANK;
        const int v = yt[idx];
        return (v < 0) ? BLANK : v;
    };
    const int base3 = 3 * lane;
    const int cm1 = labAt(base3 - 1);
    const int c0  = labAt(base3);       // class of state 6l+1
    const int c1  = labAt(base3 + 1);   // class of state 6l+3
    const int c2  = labAt(base3 + 2);   // class of state 6l+5

    // ---- per-state constants ----
    const int s0 = 6 * lane;
    const bool v0 = (s0 + 0) < Svalid;
    const bool v1 = (s0 + 1) < Svalid;
    const bool v2 = (s0 + 2) < Svalid;
    const bool v3 = (s0 + 3) < Svalid;
    const bool v4 = (s0 + 4) < Svalid;
    const bool v5 = (s0 + 5) < Svalid;
    // allow2 only on odd (label) states: ext[s]!=blank && ext[s]!=ext[s-2]
    const float M1 = ((s0 + 1) >= 2 && c0 != BLANK && c0 != cm1) ? 1.f : 0.f;
    const float M3 = ((s0 + 3) >= 2 && c1 != BLANK && c1 != c0)  ? 1.f : 0.f;
    const float M5 = ((s0 + 5) >= 2 && c2 != BLANK && c2 != c1)  ? 1.f : 0.f;

    // ---- alpha registers, t = 0 init (biased by 2^40 for early headroom) ----
    const float BIAS = __uint_as_float((unsigned)(40 + 127) << 23);  // 2^40
    float a0 = 0.f, a1 = 0.f, a2 = 0.f, a3 = 0.f, a4 = 0.f, a5 = 0.f;
    if (lane == 0) {
        a0 = (__ldg(lpb + BLANK) + EPSV) * BIAS;            // s=0 always valid
        if (ll > 0) a1 = (__ldg(lpb + c0) + EPSV) * BIAS;   // s=1 iff ll>=1
    }
    int kAcc = -40;  // accumulated power-of-2 exponent removed by renorms

    // ---- prefetch ring: slot i holds p[t] for step t with (t-1)&7 == i ----
    float pb[Dp], p0[Dp], p1[Dp], p2[Dp];
    #pragma unroll
    for (int i = 0; i < Dp; ++i) {
        const float* pt = lpb + (size_t)(1 + i) * Cc;
        pb[i] = __ldg(pt + BLANK);
        p0[i] = __ldg(pt + c0);
        p1[i] = __ldg(pt + c1);
        p2[i] = __ldg(pt + c2);
    }

    // exact power-of-2 renorm: bring warp-max exponent to +80
    auto renorm = [&]() {
        float m = fmaxf(fmaxf(fmaxf(a0, a1), fmaxf(a2, a3)), fmaxf(a4, a5));
        const unsigned mi = __reduce_max_sync(FULLMASK, __float_as_uint(m));
        const unsigned ebits = mi & 0x7f800000u;
        if (ebits != 0u) {                                   // uniform branch
            const int Ei = (int)(ebits >> 23);               // biased exponent
            // scale = 2^(80 - (Ei-127)) = 2^(207-Ei); field = 334-Ei in [207,254]
            const float rs = __uint_as_float((unsigned)(334 - Ei) << 23);
            a0 *= rs; a1 *= rs; a2 *= rs; a3 *= rs; a4 *= rs; a5 *= rs;
            kAcc += Ei - 207;                                // Ei-127-80
        }
    };

    // ---- main scan: t = 1 .. T-1, unrolled by 8, renorm every 4 steps ----
    for (int t0 = 1; t0 < Tt; t0 += 8) {
        #pragma unroll
        for (int j = 0; j < 8; ++j) {
            const int t = t0 + j;
            if (t < Tt) {
                // emissions for step t (slot j), validity folded in
                const float ebv = pb[j] + EPSV;
                const float E0 = v0 ? ebv : 0.f;
                const float E1 = v1 ? (p0[j] + EPSV) : 0.f;
                const float E2 = v2 ? ebv : 0.f;
                const float E3 = v3 ? (p1[j] + EPSV) : 0.f;
                const float E4 = v4 ? ebv : 0.f;
                const float E5 = v5 ? (p2[j] + EPSV) : 0.f;

                // refill this slot with p[t + 8]
                int tl = t + Dp; if (tl > Tt - 1) tl = Tt - 1;
                const float* pt = lpb + (size_t)tl * Cc;
                pb[j] = __ldg(pt + BLANK);
                p0[j] = __ldg(pt + c0);
                p1[j] = __ldg(pt + c1);
                p2[j] = __ldg(pt + c2);

                // cross-lane neighbor: lane l-1's a5 (= s0-1; also skip src of s0+1)
                float n1 = __shfl_up_sync(FULLMASK, a5, 1);
                n1 = (lane == 0) ? 0.f : n1;

                const float t0v = E0 * (a0 + n1);                 // blank: no skip
                const float t1v = E1 * fmaf(M1, n1, a1 + a0);
                const float t2v = E2 * (a2 + a1);
                const float t3v = E3 * fmaf(M3, a1, a3 + a2);
                const float t4v = E4 * (a4 + a3);
                const float t5v = E5 * fmaf(M5, a3, a5 + a4);
                a0 = t0v; a1 = t1v; a2 = t2v; a3 = t3v; a4 = t4v; a5 = t5v;
            }
            if (j == 3) renorm();          // 4-step renorm cadence
        }
        renorm();
    }

    // ---- epilogue: loss = -( log(a[2ll] + a[2ll-1]) + kAcc*ln2 ) ----
    const int sl = 2 * ll;
    float vl = pick6(a0, a1, a2, a3, a4, a5, sl % 6);
    vl = __shfl_sync(FULLMASK, vl, sl / 6);
    float vp = 0.f;
    if (ll > 0) {                                            // uniform
        const int sp = sl - 1;
        float t = pick6(a0, a1, a2, a3, a4, a5, sp % 6);
        vp = __shfl_sync(FULLMASK, t, sp / 6);
    }
    if (lane == 0) {
        out[b] = -(__logf(vl + vp) + (float)kAcc * 0.6931471805599453f);
    }
}

extern "C" void kernel_launch(void* const* d_in, const int* in_sizes, int n_in,
                              void* d_out, int out_size)
{
    const void* q0 = d_in[0];
    const void* q1 = d_in[1];
    const int*   y_true;
    const float* y_pred;
    if (in_sizes[0] < in_sizes[1]) {
        y_true = (const int*)q0;
        y_pred = (const float*)q1;
    } else {
        y_true = (const int*)q1;
        y_pred = (const float*)q0;
    }
    float* out = (float*)d_out;

    const int B = out_size;                 // one loss per row
    const int blocks = (B + 3) / 4;         // 4 warps (rows) per 128-thread block
    ctc_warp_kernel<<<blocks, 128>>>(y_true, y_pred, out, B);
}

// round 7
// speedup vs baseline: 4.7615x; 1.2137x over previous
#include <cuda_runtime.h>
#include <cuda_bf16.h>
#include <cstddef>

// CTC forward loss, probability-domain DP, warp-per-row, barrier-free.
// B=256, T=512, C=1024, L=64, S=129.
// R7: one-warp CTAs (256 CTAs -> all 148 SMs used, vs 64 SMs before) and
// prefetch ring deepened 8 -> 16 steps (~880cy slack > loaded DRAM latency).
// Lane l holds states 6l..6l+5 in registers; one shfl_up per step; exact
// power-of-2 renorm every 4 steps to target max 2^80; one log at the end.

#define FULLMASK 0xffffffffu
#define EPSV 1e-7f

namespace {
constexpr int Tt = 512;
constexpr int Cc = 1024;
constexpr int Ll = 64;
constexpr int BLANK = Cc - 1;
constexpr int Dp = 16;           // prefetch ring depth (steps)
}

__device__ __forceinline__ float pick6(float a0, float a1, float a2,
                                       float a3, float a4, float a5, int j) {
    float r = a0;
    r = (j == 1) ? a1 : r;
    r = (j == 2) ? a2 : r;
    r = (j == 3) ? a3 : r;
    r = (j == 4) ? a4 : r;
    r = (j == 5) ? a5 : r;
    return r;
}

__global__ __launch_bounds__(32, 1)
void ctc_warp_kernel(const int* __restrict__ y_true,
                     const float* __restrict__ y_pred,
                     float* __restrict__ out, int B)
{
    const int lane = threadIdx.x & 31;
    const int b = blockIdx.x;
    if (b >= B) return;

    const int*   yt  = y_true + b * Ll;
    const float* lpb = y_pred + (size_t)b * Tt * Cc;

    // ---- label length via ballots (Ll = 64 = 2 x 32) ----
    const int va = yt[lane];
    const int vb = yt[lane + 32];
    const int ll = __popc(__ballot_sync(FULLMASK, va != -1)) +
                   __popc(__ballot_sync(FULLMASK, vb != -1));
    const int Svalid = 2 * ll + 1;

    // ---- labels this lane needs: indices 3*lane-1 .. 3*lane+2 ----
    auto labAt = [&](int idx) -> int {
        if (idx < 0 || idx >= Ll) return BLANK;
        const int v = yt[idx];
        return (v < 0) ? BLANK : v;
    };
    const int base3 = 3 * lane;
    const int cm1 = labAt(base3 - 1);
    const int c0  = labAt(base3);       // class of state 6l+1
    const int c1  = labAt(base3 + 1);   // class of state 6l+3
    const int c2  = labAt(base3 + 2);   // class of state 6l+5

    // ---- per-state constants ----
    const int s0 = 6 * lane;
    const bool v0 = (s0 + 0) < Svalid;
    const bool v1 = (s0 + 1) < Svalid;
    const bool v2 = (s0 + 2) < Svalid;
    const bool v3 = (s0 + 3) < Svalid;
    const bool v4 = (s0 + 4) < Svalid;
    const bool v5 = (s0 + 5) < Svalid;
    // allow2 only on odd (label) states: ext[s]!=blank && ext[s]!=ext[s-2]
    const float M1 = ((s0 + 1) >= 2 && c0 != BLANK && c0 != cm1) ? 1.f : 0.f;
    const float M3 = ((s0 + 3) >= 2 && c1 != BLANK && c1 != c0)  ? 1.f : 0.f;
    const float M5 = ((s0 + 5) >= 2 && c2 != BLANK && c2 != c1)  ? 1.f : 0.f;

    // ---- alpha registers, t = 0 init (biased by 2^40 for early headroom) ----
    const float BIAS = __uint_as_float((unsigned)(40 + 127) << 23);  // 2^40
    float a0 = 0.f, a1 = 0.f, a2 = 0.f, a3 = 0.f, a4 = 0.f, a5 = 0.f;
    if (lane == 0) {
        a0 = (__ldg(lpb + BLANK) + EPSV) * BIAS;            // s=0 always valid
        if (ll > 0) a1 = (__ldg(lpb + c0) + EPSV) * BIAS;   // s=1 iff ll>=1
    }
    int kAcc = -40;  // accumulated power-of-2 exponent removed by renorms

    // ---- prefetch ring: slot i holds p[t] for step t with (t-1)&15 == i ----
    float pb[Dp], p0[Dp], p1[Dp], p2[Dp];
    #pragma unroll
    for (int i = 0; i < Dp; ++i) {
        const float* pt = lpb + (size_t)(1 + i) * Cc;
        pb[i] = __ldg(pt + BLANK);
        p0[i] = __ldg(pt + c0);
        p1[i] = __ldg(pt + c1);
        p2[i] = __ldg(pt + c2);
    }

    // exact power-of-2 renorm: bring warp-max exponent to +80
    auto renorm = [&]() {
        float m = fmaxf(fmaxf(fmaxf(a0, a1), fmaxf(a2, a3)), fmaxf(a4, a5));
        const unsigned mi = __reduce_max_sync(FULLMASK, __float_as_uint(m));
        const unsigned ebits = mi & 0x7f800000u;
        if (ebits != 0u) {                                   // uniform branch
            const int Ei = (int)(ebits >> 23);               // biased exponent
            // scale = 2^(80 - (Ei-127)) = 2^(207-Ei); field = 334-Ei
            const float rs = __uint_as_float((unsigned)(334 - Ei) << 23);
            a0 *= rs; a1 *= rs; a2 *= rs; a3 *= rs; a4 *= rs; a5 *= rs;
            kAcc += Ei - 207;                                // Ei-127-80
        }
    };

    // ---- main scan: t = 1 .. T-1, unrolled by 16, renorm every 4 steps ----
    for (int t0 = 1; t0 < Tt; t0 += Dp) {
        #pragma unroll
        for (int j = 0; j < Dp; ++j) {
            const int t = t0 + j;
            if (t < Tt) {
                // emissions for step t (slot j), validity folded in
                const float ebv = pb[j] + EPSV;
                const float E0 = v0 ? ebv : 0.f;
                const float E1 = v1 ? (p0[j] + EPSV) : 0.f;
                const float E2 = v2 ? ebv : 0.f;
                const float E3 = v3 ? (p1[j] + EPSV) : 0.f;
                const float E4 = v4 ? ebv : 0.f;
                const float E5 = v5 ? (p2[j] + EPSV) : 0.f;

                // refill this slot with p[t + Dp]
                int tl = t + Dp; if (tl > Tt - 1) tl = Tt - 1;
                const float* pt = lpb + (size_t)tl * Cc;
                pb[j] = __ldg(pt + BLANK);
                p0[j] = __ldg(pt + c0);
                p1[j] = __ldg(pt + c1);
                p2[j] = __ldg(pt + c2);

                // cross-lane neighbor: lane l-1's a5 (= s0-1; also skip src of s0+1)
                float n1 = __shfl_up_sync(FULLMASK, a5, 1);
                n1 = (lane == 0) ? 0.f : n1;

                const float t0v = E0 * (a0 + n1);                 // blank: no skip
                const float t1v = E1 * fmaf(M1, n1, a1 + a0);
                const float t2v = E2 * (a2 + a1);
                const float t3v = E3 * fmaf(M3, a1, a3 + a2);
                const float t4v = E4 * (a4 + a3);
                const float t5v = E5 * fmaf(M5, a3, a5 + a4);
                a0 = t0v; a1 = t1v; a2 = t2v; a3 = t3v; a4 = t4v; a5 = t5v;
            }
            if ((j & 3) == 3) renorm();    // 4-step renorm cadence
        }
    }

    // ---- epilogue: loss = -( log(a[2ll] + a[2ll-1]) + kAcc*ln2 ) ----
    const int sl = 2 * ll;
    float vl = pick6(a0, a1, a2, a3, a4, a5, sl % 6);
    vl = __shfl_sync(FULLMASK, vl, sl / 6);
    float vp = 0.f;
    if (ll > 0) {                                            // uniform
        const int sp = sl - 1;
        float t = pick6(a0, a1, a2, a3, a4, a5, sp % 6);
        vp = __shfl_sync(FULLMASK, t, sp / 6);
    }
    if (lane == 0) {
        out[b] = -(__logf(vl + vp) + (float)kAcc * 0.6931471805599453f);
    }
}

extern "C" void kernel_launch(void* const* d_in, const int* in_sizes, int n_in,
                              void* d_out, int out_size)
{
    const void* q0 = d_in[0];
    const void* q1 = d_in[1];
    const int*   y_true;
    const float* y_pred;
    if (in_sizes[0] < in_sizes[1]) {
        y_true = (const int*)q0;
        y_pred = (const float*)q1;
    } else {
        y_true = (const int*)q1;
        y_pred = (const float*)q0;
    }
    float* out = (float*)d_out;

    const int B = out_size;                 // one loss per row
    ctc_warp_kernel<<<B, 32>>>(y_true, y_pred, out, B);  // 1 warp per CTA
}